// round 1
// baseline (speedup 1.0000x reference)
#include <cuda_runtime.h>
#include <cuda_bf16.h>
#include <math.h>

// Problem constants
#define PB 32
#define PN 4096
#define PD 768
#define PC 10
#define PK 16

// Scratch: per-(b,n) scores. 32*4096 floats = 512 KB. __device__ global (no alloc allowed).
__device__ float g_scores[PB * PN];

// ---------------------------------------------------------------------------
// Kernel 1: scores s[b,n] = dot(H[b,n,:], w) + b_score. One warp per row.
// Also zero-initializes the A region of the output (poisoned by harness).
// ---------------------------------------------------------------------------
__global__ void __launch_bounds__(256) score_kernel(
    const float* __restrict__ H,
    const float* __restrict__ w_score,
    const float* __restrict__ b_score,
    float* __restrict__ A_out)   // d_out + 320, size PB*PN
{
    const int tid_global = blockIdx.x * blockDim.x + threadIdx.x;
    const int warp = tid_global >> 5;
    const int lane = threadIdx.x & 31;

    // Zero the A output region (exactly PB*PN threads do one element each).
    if (tid_global < PB * PN) A_out[tid_global] = 0.0f;

    if (warp >= PB * PN) return;

    const float4* __restrict__ h4 = (const float4*)(H + (size_t)warp * PD);
    const float4* __restrict__ w4 = (const float4*)w_score;

    float sum = 0.0f;
    #pragma unroll
    for (int k = 0; k < PD / 128; k++) {        // 768/4 = 192 float4; 192/32 = 6 per lane
        float4 a = h4[lane + k * 32];
        float4 b = __ldg(&w4[lane + k * 32]);
        sum += a.x * b.x + a.y * b.y + a.z * b.z + a.w * b.w;
    }
    #pragma unroll
    for (int o = 16; o > 0; o >>= 1)
        sum += __shfl_down_sync(0xFFFFFFFFu, sum, o);

    if (lane == 0) g_scores[warp] = sum + b_score[0];
}

// ---------------------------------------------------------------------------
// Kernel 2: per-batch top-16 (stable, ties -> lower index, matching jax
// top_k), scatter A, gather+mean top rows, classifier GEMV. 1 CTA per batch.
// ---------------------------------------------------------------------------
__global__ void __launch_bounds__(256) topk_epilogue_kernel(
    const float* __restrict__ H,
    const float* __restrict__ W_cls,   // [D, C] row-major: W[d*C + c]
    const float* __restrict__ b_cls,   // [C]
    float* __restrict__ logits_out,    // d_out, size PB*PC
    float* __restrict__ A_out)         // d_out + PB*PC, size PB*PN
{
    const int b = blockIdx.x;
    const int tid = threadIdx.x;

    __shared__ float sc[PN];           // 16 KB
    __shared__ float rv[256];
    __shared__ int   ri[256];
    __shared__ int   top[PK];
    __shared__ float m[PD];            // mean vector

    const float* __restrict__ sb = g_scores + b * PN;
    for (int i = tid; i < PN; i += 256) sc[i] = sb[i];
    __syncthreads();

    // 16 sequential block-wide argmax passes
    for (int it = 0; it < PK; it++) {
        float bv = -INFINITY;
        int   bi = 0x7FFFFFFF;
        for (int i = tid; i < PN; i += 256) {
            float v = sc[i];
            if (v > bv) { bv = v; bi = i; }   // strided forward scan keeps lowest idx on ties
        }
        rv[tid] = bv; ri[tid] = bi;
        __syncthreads();
        #pragma unroll
        for (int s = 128; s > 0; s >>= 1) {
            if (tid < s) {
                float ov = rv[tid + s]; int oi = ri[tid + s];
                if (ov > rv[tid] || (ov == rv[tid] && oi < ri[tid])) {
                    rv[tid] = ov; ri[tid] = oi;
                }
            }
            __syncthreads();
        }
        if (tid == 0) { top[it] = ri[0]; sc[ri[0]] = -INFINITY; }
        __syncthreads();
    }

    // Scatter attention mask A: 1/K at each top index
    if (tid < PK) A_out[b * PN + top[tid]] = 1.0f / (float)PK;

    // Mean of the K gathered rows: m[d] = (1/K) * sum_j H[b, top[j], d]
    for (int d = tid; d < PD; d += 256) {
        float s = 0.0f;
        #pragma unroll
        for (int j = 0; j < PK; j++) {
            s += H[((size_t)b * PN + top[j]) * PD + d];
        }
        m[d] = s * (1.0f / (float)PK);
    }
    __syncthreads();

    // logits[b,c] = b_cls[c] + sum_d m[d] * W_cls[d,c]
    if (tid < PC) {
        float acc = b_cls[tid];
        for (int d = 0; d < PD; d++)
            acc += m[d] * W_cls[d * PC + tid];
        logits_out[b * PC + tid] = acc;
    }
}

// ---------------------------------------------------------------------------
// Launch
// Inputs (metadata order): H [B,N,D] f32, w_score [D] f32, b_score [] f32,
//                          W_cls [D,C] f32, b_cls [C] f32.
// Output: logits [B,C] (320 floats) followed by A [B,N,1] (131072 floats).
// ---------------------------------------------------------------------------
extern "C" void kernel_launch(void* const* d_in, const int* in_sizes, int n_in,
                              void* d_out, int out_size)
{
    const float* H       = (const float*)d_in[0];
    const float* w_score = (const float*)d_in[1];
    const float* b_score = (const float*)d_in[2];
    const float* W_cls   = (const float*)d_in[3];
    const float* b_cls   = (const float*)d_in[4];

    float* logits_out = (float*)d_out;
    float* A_out      = (float*)d_out + PB * PC;

    // Kernel 1: one warp per row -> 8 rows per 256-thread block
    const int rows = PB * PN;                 // 131072
    const int blocks1 = (rows + 7) / 8;       // 16384
    score_kernel<<<blocks1, 256>>>(H, w_score, b_score, A_out);

    // Kernel 2: one block per batch
    topk_epilogue_kernel<<<PB, 256>>>(H, W_cls, b_cls, logits_out, A_out);
}

// round 3
// speedup vs baseline: 1.3695x; 1.3695x over previous
#include <cuda_runtime.h>
#include <cuda_bf16.h>
#include <math.h>

// Problem constants
#define PB 32
#define PN 4096
#define PD 768
#define PC 10
#define PK 16

// Scratch: per-(b,n) scores. 32*4096 floats = 512 KB.
__device__ float g_scores[PB * PN];

// ---------------------------------------------------------------------------
// Kernel 1: scores s[b,n] = dot(H[b,n,:], w) + b_score. One warp per row.
// Also zero-initializes the A region of the output (poisoned by harness).
// Measured at ~7.6 TB/s (HBM roofline) in R1 — do not touch.
// ---------------------------------------------------------------------------
__global__ void __launch_bounds__(256) score_kernel(
    const float* __restrict__ H,
    const float* __restrict__ w_score,
    const float* __restrict__ b_score,
    float* __restrict__ A_out)   // d_out + 320, size PB*PN
{
    const int tid_global = blockIdx.x * blockDim.x + threadIdx.x;
    const int warp = tid_global >> 5;
    const int lane = threadIdx.x & 31;

    if (tid_global < PB * PN) A_out[tid_global] = 0.0f;

    if (warp >= PB * PN) return;

    const float4* __restrict__ h4 = (const float4*)(H + (size_t)warp * PD);
    const float4* __restrict__ w4 = (const float4*)w_score;

    float sum = 0.0f;
    #pragma unroll
    for (int k = 0; k < PD / 128; k++) {        // 6 float4 per lane
        float4 a = h4[lane + k * 32];
        float4 b = __ldg(&w4[lane + k * 32]);
        sum += a.x * b.x + a.y * b.y + a.z * b.z + a.w * b.w;
    }
    #pragma unroll
    for (int o = 16; o > 0; o >>= 1)
        sum += __shfl_down_sync(0xFFFFFFFFu, sum, o);

    if (lane == 0) g_scores[warp] = sum + b_score[0];
}

// ---------------------------------------------------------------------------
// Orderable 64-bit key: larger key <=> (larger score, then lower index).
// Keys are unique (index in low bits). 0 is a safe "removed" sentinel
// (real keys always have nonzero low bits: 0xFFFFFFFF - idx >= 0xFFFFEFFF).
// ---------------------------------------------------------------------------
__device__ __forceinline__ unsigned long long pack_key(float s, unsigned idx) {
    unsigned u = __float_as_uint(s);
    u = (u & 0x80000000u) ? ~u : (u | 0x80000000u);
    return ((unsigned long long)u << 32) | (0xFFFFFFFFu - idx);
}
__device__ __forceinline__ unsigned key_idx(unsigned long long k) {
    return 0xFFFFFFFFu - (unsigned)(k & 0xFFFFFFFFu);
}

// ---------------------------------------------------------------------------
// Kernel 2: per-batch top-16 via register-resident hierarchical selection,
// scatter A, gather+mean top rows, classifier GEMV. 1 CTA per batch.
// ---------------------------------------------------------------------------
__global__ void __launch_bounds__(256) topk_epilogue_kernel(
    const float* __restrict__ H,
    const float* __restrict__ W_cls,   // [D, C] row-major
    const float* __restrict__ b_cls,   // [C]
    float* __restrict__ logits_out,    // d_out, size PB*PC
    float* __restrict__ A_out)         // d_out + PB*PC, size PB*PN
{
    const int b    = blockIdx.x;
    const int tid  = threadIdx.x;
    const int warp = tid >> 5;
    const int lane = tid & 31;
    const unsigned FULL = 0xFFFFFFFFu;

    __shared__ unsigned long long cand[8 * PK];  // per-warp top-16 candidates
    __shared__ int   top[PK];
    __shared__ float m[PD];

    // ---- Phase 1: per-warp top-16 over 512 scores (16 regs/lane) ----
    {
        unsigned long long v[16];
        const float* __restrict__ sb = g_scores + b * PN + warp * 512;
        #pragma unroll
        for (int j = 0; j < 16; j++) {
            unsigned idx = (unsigned)(warp * 512 + j * 32 + lane);
            v[j] = pack_key(sb[j * 32 + lane], idx);   // coalesced
        }
        // lane-local running best
        unsigned long long bk = v[0]; int bj = 0;
        #pragma unroll
        for (int j = 1; j < 16; j++) if (v[j] > bk) { bk = v[j]; bj = j; }

        for (int it = 0; it < PK; it++) {
            unsigned long long mx = bk;
            #pragma unroll
            for (int o = 16; o > 0; o >>= 1) {
                unsigned long long t = __shfl_xor_sync(FULL, mx, o);
                if (t > mx) mx = t;
            }
            unsigned win = __ballot_sync(FULL, bk == mx);
            int wlane = __ffs(win) - 1;
            if (lane == wlane) {                 // winner invalidates + rescans
                v[bj] = 0ull;
                bk = v[0]; bj = 0;
                #pragma unroll
                for (int j = 1; j < 16; j++) if (v[j] > bk) { bk = v[j]; bj = j; }
            }
            if (lane == 0) cand[warp * PK + it] = mx;
        }
    }
    __syncthreads();

    // ---- Phase 2: warp 0 merges 128 candidates -> global top-16 ----
    if (warp == 0) {
        unsigned long long v[4];
        #pragma unroll
        for (int j = 0; j < 4; j++) v[j] = cand[j * 32 + lane];
        unsigned long long bk = v[0]; int bj = 0;
        #pragma unroll
        for (int j = 1; j < 4; j++) if (v[j] > bk) { bk = v[j]; bj = j; }

        for (int it = 0; it < PK; it++) {
            unsigned long long mx = bk;
            #pragma unroll
            for (int o = 16; o > 0; o >>= 1) {
                unsigned long long t = __shfl_xor_sync(FULL, mx, o);
                if (t > mx) mx = t;
            }
            unsigned win = __ballot_sync(FULL, bk == mx);
            int wlane = __ffs(win) - 1;
            if (lane == wlane) {
                v[bj] = 0ull;
                bk = v[0]; bj = 0;
                #pragma unroll
                for (int j = 1; j < 4; j++) if (v[j] > bk) { bk = v[j]; bj = j; }
            }
            if (lane == 0) top[it] = (int)key_idx(mx);
        }
    }
    __syncthreads();

    // ---- Scatter attention mask A ----
    if (tid < PK) A_out[b * PN + top[tid]] = 1.0f / (float)PK;

    // ---- Mean of the K gathered rows (float4 vectorized) ----
    if (tid < PD / 4) {                          // 192 threads
        const float4* __restrict__ H4 = (const float4*)H;
        float4 s = make_float4(0.f, 0.f, 0.f, 0.f);
        #pragma unroll
        for (int j = 0; j < PK; j++) {
            float4 h = H4[((size_t)b * PN + top[j]) * (PD / 4) + tid];
            s.x += h.x; s.y += h.y; s.z += h.z; s.w += h.w;
        }
        const float inv = 1.0f / (float)PK;
        m[tid * 4 + 0] = s.x * inv;
        m[tid * 4 + 1] = s.y * inv;
        m[tid * 4 + 2] = s.z * inv;
        m[tid * 4 + 3] = s.w * inv;
    }
    __syncthreads();

    // ---- Classifier GEMV: warp-per-class (warps 0,1 take a second class) ----
    for (int c = warp; c < PC; c += 8) {
        float acc = 0.0f;
        #pragma unroll 4
        for (int d = lane; d < PD; d += 32)
            acc += m[d] * __ldg(&W_cls[d * PC + c]);
        #pragma unroll
        for (int o = 16; o > 0; o >>= 1)
            acc += __shfl_down_sync(FULL, acc, o);
        if (lane == 0) logits_out[b * PC + c] = acc + b_cls[c];
    }
}

// ---------------------------------------------------------------------------
// Launch
// Inputs (metadata order): H [B,N,D] f32, w_score [D] f32, b_score [] f32,
//                          W_cls [D,C] f32, b_cls [C] f32.
// Output: logits [B,C] (320 floats) followed by A [B,N,1] (131072 floats).
// ---------------------------------------------------------------------------
extern "C" void kernel_launch(void* const* d_in, const int* in_sizes, int n_in,
                              void* d_out, int out_size)
{
    const float* H       = (const float*)d_in[0];
    const float* w_score = (const float*)d_in[1];
    const float* b_score = (const float*)d_in[2];
    const float* W_cls   = (const float*)d_in[3];
    const float* b_cls   = (const float*)d_in[4];

    float* logits_out = (float*)d_out;
    float* A_out      = (float*)d_out + PB * PC;

    const int rows = PB * PN;                 // 131072 rows, 1 warp each
    const int blocks1 = (rows + 7) / 8;       // 16384 blocks of 256
    score_kernel<<<blocks1, 256>>>(H, w_score, b_score, A_out);

    topk_epilogue_kernel<<<PB, 256>>>(H, W_cls, b_cls, logits_out, A_out);
}

// round 4
// speedup vs baseline: 1.4479x; 1.0572x over previous
#include <cuda_runtime.h>
#include <cuda_bf16.h>
#include <math.h>

// Problem constants
#define PB 32
#define PN 4096
#define PD 768
#define PC 10
#define PK 16

// Scratch: per-(b,n) scores. 32*4096 floats = 512 KB.
__device__ float g_scores[PB * PN];

// ---------------------------------------------------------------------------
// Kernel 1: scores s[b,n] = dot(H[b,n,:], w) + b_score. One warp per row.
// Also zero-initializes the A region of the output (poisoned by harness).
// Measured ~6.8 TB/s (85% of HBM spec) — at roofline, do not touch.
// ---------------------------------------------------------------------------
__global__ void __launch_bounds__(256) score_kernel(
    const float* __restrict__ H,
    const float* __restrict__ w_score,
    const float* __restrict__ b_score,
    float* __restrict__ A_out)   // d_out + 320, size PB*PN
{
    const int tid_global = blockIdx.x * blockDim.x + threadIdx.x;
    const int warp = tid_global >> 5;
    const int lane = threadIdx.x & 31;

    if (tid_global < PB * PN) A_out[tid_global] = 0.0f;

    if (warp >= PB * PN) return;

    const float4* __restrict__ h4 = (const float4*)(H + (size_t)warp * PD);
    const float4* __restrict__ w4 = (const float4*)w_score;

    float sum = 0.0f;
    #pragma unroll
    for (int k = 0; k < PD / 128; k++) {        // 6 float4 per lane
        float4 a = h4[lane + k * 32];
        float4 b = __ldg(&w4[lane + k * 32]);
        sum += a.x * b.x + a.y * b.y + a.z * b.z + a.w * b.w;
    }
    #pragma unroll
    for (int o = 16; o > 0; o >>= 1)
        sum += __shfl_down_sync(0xFFFFFFFFu, sum, o);

    if (lane == 0) g_scores[warp] = sum + b_score[0];
}

// ---------------------------------------------------------------------------
// Orderable 64-bit key: larger key <=> (larger score, then lower index).
// Keys are unique (index in low bits), so value-matched invalidation is safe.
// 0 is a safe "removed" sentinel (real low bits >= 0xFFFFEFFF).
// ---------------------------------------------------------------------------
__device__ __forceinline__ unsigned long long pack_key(float s, unsigned idx) {
    unsigned u = __float_as_uint(s);
    u = (u & 0x80000000u) ? ~u : (u | 0x80000000u);
    return ((unsigned long long)u << 32) | (0xFFFFFFFFu - idx);
}
__device__ __forceinline__ unsigned key_idx(unsigned long long k) {
    return 0xFFFFFFFFu - (unsigned)(k & 0xFFFFFFFFu);
}

// ---------------------------------------------------------------------------
// Kernel 2: per-batch top-16, scatter A, gather+mean top rows, classifier
// GEMV. 1 CTA per batch. All selection state strictly register-resident:
// no dynamic array indexing anywhere (the R3 version spilled to local mem).
// ---------------------------------------------------------------------------
__global__ void __launch_bounds__(256) topk_epilogue_kernel(
    const float* __restrict__ H,
    const float* __restrict__ W_cls,   // [D, C] row-major
    const float* __restrict__ b_cls,   // [C]
    float* __restrict__ logits_out,    // d_out, size PB*PC
    float* __restrict__ A_out)         // d_out + PB*PC, size PB*PN
{
    const int b    = blockIdx.x;
    const int tid  = threadIdx.x;
    const int warp = tid >> 5;
    const int lane = tid & 31;
    const unsigned FULL = 0xFFFFFFFFu;

    __shared__ unsigned long long cand[8 * PK];  // per-warp top-16 candidates
    __shared__ int   top[PK];
    __shared__ float m[PD];

    // ---- Phase 1: per-warp top-16 over 512 scores (16 regs/lane) ----
    {
        unsigned long long v[16];
        const float* __restrict__ sb = g_scores + b * PN + warp * 512;
        #pragma unroll
        for (int j = 0; j < 16; j++) {
            unsigned idx = (unsigned)(warp * 512 + j * 32 + lane);
            v[j] = pack_key(sb[j * 32 + lane], idx);   // coalesced
        }

        #pragma unroll
        for (int it = 0; it < PK; it++) {
            // lane-local max: fully unrolled compare tree, register-only
            unsigned long long bk = v[0];
            #pragma unroll
            for (int j = 1; j < 16; j++) bk = (v[j] > bk) ? v[j] : bk;
            // warp max
            unsigned long long mx = bk;
            #pragma unroll
            for (int o = 16; o > 0; o >>= 1) {
                unsigned long long t = __shfl_xor_sync(FULL, mx, o);
                mx = (t > mx) ? t : mx;
            }
            // invalidate: keys unique -> exactly one lane clears one slot
            #pragma unroll
            for (int j = 0; j < 16; j++) if (v[j] == mx) v[j] = 0ull;
            if (lane == 0) cand[warp * PK + it] = mx;
        }
    }
    __syncthreads();

    // ---- Phase 2: warp 0 merges 128 candidates -> global top-16 ----
    if (warp == 0) {
        unsigned long long v[4];
        #pragma unroll
        for (int j = 0; j < 4; j++) v[j] = cand[j * 32 + lane];

        #pragma unroll
        for (int it = 0; it < PK; it++) {
            unsigned long long bk = v[0];
            #pragma unroll
            for (int j = 1; j < 4; j++) bk = (v[j] > bk) ? v[j] : bk;
            unsigned long long mx = bk;
            #pragma unroll
            for (int o = 16; o > 0; o >>= 1) {
                unsigned long long t = __shfl_xor_sync(FULL, mx, o);
                mx = (t > mx) ? t : mx;
            }
            #pragma unroll
            for (int j = 0; j < 4; j++) if (v[j] == mx) v[j] = 0ull;
            if (lane == 0) top[it] = (int)key_idx(mx);
        }
    }
    __syncthreads();

    // ---- Scatter attention mask A ----
    if (tid < PK) A_out[b * PN + top[tid]] = 1.0f / (float)PK;

    // ---- Mean of the K gathered rows (float4 vectorized) ----
    if (tid < PD / 4) {                          // 192 threads
        const float4* __restrict__ H4 = (const float4*)H;
        float4 s = make_float4(0.f, 0.f, 0.f, 0.f);
        #pragma unroll
        for (int j = 0; j < PK; j++) {
            float4 h = H4[((size_t)b * PN + top[j]) * (PD / 4) + tid];
            s.x += h.x; s.y += h.y; s.z += h.z; s.w += h.w;
        }
        const float inv = 1.0f / (float)PK;
        m[tid * 4 + 0] = s.x * inv;
        m[tid * 4 + 1] = s.y * inv;
        m[tid * 4 + 2] = s.z * inv;
        m[tid * 4 + 3] = s.w * inv;
    }
    __syncthreads();

    // ---- Classifier GEMV: warp-per-class ----
    for (int c = warp; c < PC; c += 8) {
        float acc = 0.0f;
        #pragma unroll 4
        for (int d = lane; d < PD; d += 32)
            acc += m[d] * __ldg(&W_cls[d * PC + c]);
        #pragma unroll
        for (int o = 16; o > 0; o >>= 1)
            acc += __shfl_down_sync(FULL, acc, o);
        if (lane == 0) logits_out[b * PC + c] = acc + b_cls[c];
    }
}

// ---------------------------------------------------------------------------
// Launch
// Inputs (metadata order): H [B,N,D] f32, w_score [D] f32, b_score [] f32,
//                          W_cls [D,C] f32, b_cls [C] f32.
// Output: logits [B,C] (320 floats) followed by A [B,N,1] (131072 floats).
// ---------------------------------------------------------------------------
extern "C" void kernel_launch(void* const* d_in, const int* in_sizes, int n_in,
                              void* d_out, int out_size)
{
    const float* H       = (const float*)d_in[0];
    const float* w_score = (const float*)d_in[1];
    const float* b_score = (const float*)d_in[2];
    const float* W_cls   = (const float*)d_in[3];
    const float* b_cls   = (const float*)d_in[4];

    float* logits_out = (float*)d_out;
    float* A_out      = (float*)d_out + PB * PC;

    const int rows = PB * PN;                 // 131072 rows, 1 warp each
    const int blocks1 = (rows + 7) / 8;       // 16384 blocks of 256
    score_kernel<<<blocks1, 256>>>(H, w_score, b_score, A_out);

    topk_epilogue_kernel<<<PB, 256>>>(H, W_cls, b_cls, logits_out, A_out);
}

// round 7
// speedup vs baseline: 1.4577x; 1.0068x over previous
#include <cuda_runtime.h>
#include <cuda_bf16.h>
#include <math.h>

// Problem constants
#define PB 32
#define PN 4096
#define PD 768
#define PC 10
#define PK 16

// Scratch: per-(b,n) scores. 32*4096 floats = 512 KB.
__device__ float g_scores[PB * PN];

// ---------------------------------------------------------------------------
// Kernel 1: scores s[b,n] = dot(H[b,n,:], w) + b_score. One warp per row.
// Also zero-initializes the A region of the output (poisoned by harness).
// Measured ~6.9 TB/s (86% of HBM spec) — at roofline, do not touch.
// ---------------------------------------------------------------------------
__global__ void __launch_bounds__(256) score_kernel(
    const float* __restrict__ H,
    const float* __restrict__ w_score,
    const float* __restrict__ b_score,
    float* __restrict__ A_out)   // d_out + 320, size PB*PN
{
    const int tid_global = blockIdx.x * blockDim.x + threadIdx.x;
    const int warp = tid_global >> 5;
    const int lane = threadIdx.x & 31;

    if (tid_global < PB * PN) A_out[tid_global] = 0.0f;

    if (warp >= PB * PN) return;

    const float4* __restrict__ h4 = (const float4*)(H + (size_t)warp * PD);
    const float4* __restrict__ w4 = (const float4*)w_score;

    float sum = 0.0f;
    #pragma unroll
    for (int k = 0; k < PD / 128; k++) {        // 6 float4 per lane
        float4 a = h4[lane + k * 32];
        float4 b = __ldg(&w4[lane + k * 32]);
        sum += a.x * b.x + a.y * b.y + a.z * b.z + a.w * b.w;
    }
    #pragma unroll
    for (int o = 16; o > 0; o >>= 1)
        sum += __shfl_down_sync(0xFFFFFFFFu, sum, o);

    if (lane == 0) g_scores[warp] = sum + b_score[0];
}

// Monotone 32-bit mapping: flip(a) > flip(b)  <=>  a > b (as floats)
__device__ __forceinline__ unsigned flip_f32(float s) {
    unsigned u = __float_as_uint(s);
    return (u & 0x80000000u) ? ~u : (u | 0x80000000u);
}

// ---------------------------------------------------------------------------
// Kernel 2: per-batch top-16 via redux.sync selection, scatter A,
// gather+mean top rows, classifier GEMV. 1 CTA per batch.
// Semantics: largest value first; ties -> lowest index (jax.lax.top_k).
// ---------------------------------------------------------------------------
__global__ void __launch_bounds__(256) topk_epilogue_kernel(
    const float* __restrict__ H,
    const float* __restrict__ W_cls,   // [D, C] row-major
    const float* __restrict__ b_cls,   // [C]
    float* __restrict__ logits_out,    // d_out, size PB*PC
    float* __restrict__ A_out)         // d_out + PB*PC, size PB*PN
{
    const int b    = blockIdx.x;
    const int tid  = threadIdx.x;
    const int warp = tid >> 5;
    const int lane = tid & 31;
    const unsigned FULL = 0xFFFFFFFFu;
    const unsigned BIGI = 0xFFFFFFFFu;

    __shared__ unsigned cand_v[8 * PK];
    __shared__ unsigned cand_i[8 * PK];
    __shared__ int   top[PK];
    __shared__ float m[PD];

    // ---- Phase 1: per-warp top-16 over 512 scores (16 x u32 regs/lane) ----
    {
        unsigned kv[16];
        const float* __restrict__ sb = g_scores + b * PN + warp * 512;
        #pragma unroll
        for (int j = 0; j < 16; j++)
            kv[j] = flip_f32(sb[j * 32 + lane]);          // coalesced
        const unsigned base = (unsigned)(warp * 512 + lane);

        #pragma unroll
        for (int it = 0; it < PK; it++) {
            // lane-local best: ascending scan, strict > keeps lowest slot on tie
            unsigned bv = kv[0]; unsigned bj = 0;
            #pragma unroll
            for (int j = 1; j < 16; j++)
                if (kv[j] > bv) { bv = kv[j]; bj = (unsigned)j; }
            // warp-wide max value (HW redux)
            unsigned mx = __reduce_max_sync(FULL, bv);
            // lowest global index among lanes holding mx (HW redux)
            unsigned myidx = (bv == mx) ? (base + bj * 32) : BIGI;
            unsigned widx  = __reduce_min_sync(FULL, myidx);
            // invalidate winner slot (slot-index match; no dynamic indexing)
            unsigned r = widx - base;                      // == j*32 iff mine
            #pragma unroll
            for (int j = 0; j < 16; j++)
                if (r == (unsigned)(j * 32)) kv[j] = 0u;
            if (lane == 0) { cand_v[warp * PK + it] = mx; cand_i[warp * PK + it] = widx; }
        }
    }
    __syncthreads();

    // ---- Phase 2: warp 0 merges 128 (value,idx) pairs -> global top-16 ----
    if (warp == 0) {
        unsigned vv[4], vi[4];
        #pragma unroll
        for (int j = 0; j < 4; j++) {
            vv[j] = cand_v[j * 32 + lane];
            vi[j] = cand_i[j * 32 + lane];
        }
        #pragma unroll
        for (int it = 0; it < PK; it++) {
            // lane-local best pair: larger value, tie -> lower index
            unsigned bv = vv[0], bi = vi[0];
            #pragma unroll
            for (int j = 1; j < 4; j++) {
                bool better = (vv[j] > bv) || (vv[j] == bv && vi[j] < bi);
                if (better) { bv = vv[j]; bi = vi[j]; }
            }
            unsigned mx = __reduce_max_sync(FULL, bv);
            unsigned myidx = (bv == mx) ? bi : BIGI;
            unsigned widx  = __reduce_min_sync(FULL, myidx);
            #pragma unroll
            for (int j = 0; j < 4; j++)
                if (vv[j] == mx && vi[j] == widx) { vv[j] = 0u; vi[j] = BIGI; }
            if (lane == 0) top[it] = (int)widx;
        }
    }
    __syncthreads();

    // ---- Scatter attention mask A ----
    if (tid < PK) A_out[b * PN + top[tid]] = 1.0f / (float)PK;

    // ---- Mean of the K gathered rows (float4 vectorized) ----
    if (tid < PD / 4) {                          // 192 threads
        const float4* __restrict__ H4 = (const float4*)H;
        float4 s = make_float4(0.f, 0.f, 0.f, 0.f);
        #pragma unroll
        for (int j = 0; j < PK; j++) {
            float4 h = H4[((size_t)b * PN + top[j]) * (PD / 4) + tid];
            s.x += h.x; s.y += h.y; s.z += h.z; s.w += h.w;
        }
        const float inv = 1.0f / (float)PK;
        m[tid * 4 + 0] = s.x * inv;
        m[tid * 4 + 1] = s.y * inv;
        m[tid * 4 + 2] = s.z * inv;
        m[tid * 4 + 3] = s.w * inv;
    }
    __syncthreads();

    // ---- Classifier GEMV: warp-per-class ----
    for (int c = warp; c < PC; c += 8) {
        float acc = 0.0f;
        #pragma unroll 4
        for (int d = lane; d < PD; d += 32)
            acc += m[d] * __ldg(&W_cls[d * PC + c]);
        #pragma unroll
        for (int o = 16; o > 0; o >>= 1)
            acc += __shfl_down_sync(FULL, acc, o);
        if (lane == 0) logits_out[b * PC + c] = acc + b_cls[c];
    }
}

// ---------------------------------------------------------------------------
// Launch
// Inputs (metadata order): H [B,N,D] f32, w_score [D] f32, b_score [] f32,
//                          W_cls [D,C] f32, b_cls [C] f32.
// Output: logits [B,C] (320 floats) followed by A [B,N,1] (131072 floats).
// ---------------------------------------------------------------------------
extern "C" void kernel_launch(void* const* d_in, const int* in_sizes, int n_in,
                              void* d_out, int out_size)
{
    const float* H       = (const float*)d_in[0];
    const float* w_score = (const float*)d_in[1];
    const float* b_score = (const float*)d_in[2];
    const float* W_cls   = (const float*)d_in[3];
    const float* b_cls   = (const float*)d_in[4];

    float* logits_out = (float*)d_out;
    float* A_out      = (float*)d_out + PB * PC;

    const int rows = PB * PN;                 // 131072 rows, 1 warp each
    const int blocks1 = (rows + 7) / 8;       // 16384 blocks of 256
    score_kernel<<<blocks1, 256>>>(H, w_score, b_score, A_out);

    topk_epilogue_kernel<<<PB, 256>>>(H, W_cls, b_cls, logits_out, A_out);
}

// round 9
// speedup vs baseline: 1.5364x; 1.0540x over previous
#include <cuda_runtime.h>
#include <cuda_bf16.h>
#include <cuda_pipeline.h>
#include <math.h>

// Problem constants
#define PB 32
#define PN 4096
#define PD 768
#define PC 10
#define PK 16

// Scratch: per-(b,n) pre-flipped scores (monotone u32). 512 KB.
__device__ unsigned g_scores_u[PB * PN];

// Monotone 32-bit mapping: flip(a) > flip(b)  <=>  a > b (as floats)
__device__ __forceinline__ unsigned flip_f32(float s) {
    unsigned u = __float_as_uint(s);
    return (u & 0x80000000u) ? ~u : (u | 0x80000000u);
}

// ---------------------------------------------------------------------------
// Kernel 1: scores s[b,n] = dot(H[b,n,:], w) + b_score. One warp per row.
// H read with __ldcs (streaming) so it does NOT evict g_scores/A from L2.
// Also zero-initializes the A region of the output (poisoned by harness).
// ---------------------------------------------------------------------------
__global__ void __launch_bounds__(256) score_kernel(
    const float* __restrict__ H,
    const float* __restrict__ w_score,
    const float* __restrict__ b_score,
    float* __restrict__ A_out)   // d_out + 320, size PB*PN
{
    const int tid_global = blockIdx.x * blockDim.x + threadIdx.x;
    const int warp = tid_global >> 5;
    const int lane = threadIdx.x & 31;

    if (tid_global < PB * PN) A_out[tid_global] = 0.0f;

    if (warp >= PB * PN) return;

    const float4* __restrict__ h4 = (const float4*)(H + (size_t)warp * PD);
    const float4* __restrict__ w4 = (const float4*)w_score;

    float sum = 0.0f;
    #pragma unroll
    for (int k = 0; k < PD / 128; k++) {        // 6 float4 per lane
        float4 a = __ldcs(&h4[lane + k * 32]);  // streaming: evict-first
        float4 b = __ldg(&w4[lane + k * 32]);
        sum += a.x * b.x + a.y * b.y + a.z * b.z + a.w * b.w;
    }
    #pragma unroll
    for (int o = 16; o > 0; o >>= 1)
        sum += __shfl_down_sync(0xFFFFFFFFu, sum, o);

    if (lane == 0) g_scores_u[warp] = flip_f32(sum + b_score[0]);
}

// ---------------------------------------------------------------------------
// Kernel 2: per-batch top-16 + A scatter + gather/mean + classifier.
// 1 CTA per batch. Restructured for latency:
//  - W_cls prefetched to smem via cp.async, hidden behind selection
//  - phase-2 merge run redundantly by ALL warps (uniform-register results)
//  - gather by all 8 warps feeding per-warp partial GEMV; 2 barriers total
// Semantics: largest value first; ties -> lowest index (jax.lax.top_k).
// ---------------------------------------------------------------------------
__global__ void __launch_bounds__(256) topk_epilogue_kernel(
    const float* __restrict__ H,
    const float* __restrict__ W_cls,   // [D, C] row-major
    const float* __restrict__ b_cls,   // [C]
    float* __restrict__ logits_out,    // d_out, size PB*PC
    float* __restrict__ A_out)         // d_out + PB*PC, size PB*PN
{
    const int b    = blockIdx.x;
    const int tid  = threadIdx.x;
    const int warp = tid >> 5;
    const int lane = tid & 31;
    const unsigned FULL = 0xFFFFFFFFu;
    const unsigned BIGI = 0xFFFFFFFFu;

    __shared__ __align__(16) float sW[PD * PC];  // 30720 B
    __shared__ unsigned cand_v[8 * PK];
    __shared__ unsigned cand_i[8 * PK];
    __shared__ float partial[8][PC];

    // ---- 0. Kick off W_cls -> smem prefetch (fire-and-forget) ----
    {
        const float4* __restrict__ Wg = (const float4*)W_cls;
        float4* Ws = (float4*)sW;
        #pragma unroll
        for (int i = 0; i < 8; i++) {
            int idx = tid + i * 256;               // 1920 float4 total
            if (idx < (PD * PC) / 4)
                __pipeline_memcpy_async(&Ws[idx], &Wg[idx], 16);
        }
        __pipeline_commit();
    }

    // ---- 1. Phase 1: per-warp top-16 over 512 scores (16 u32 regs/lane) ----
    {
        unsigned kv[16];
        const unsigned* __restrict__ sb = g_scores_u + b * PN + warp * 512;
        #pragma unroll
        for (int j = 0; j < 16; j++)
            kv[j] = sb[j * 32 + lane];             // coalesced, L2-resident
        const unsigned base = (unsigned)(warp * 512 + lane);

        #pragma unroll
        for (int it = 0; it < PK; it++) {
            unsigned bv = kv[0]; unsigned bj = 0;
            #pragma unroll
            for (int j = 1; j < 16; j++)
                if (kv[j] > bv) { bv = kv[j]; bj = (unsigned)j; }
            unsigned mx = __reduce_max_sync(FULL, bv);
            unsigned myidx = (bv == mx) ? (base + bj * 32) : BIGI;
            unsigned widx  = __reduce_min_sync(FULL, myidx);
            unsigned r = widx - base;              // == j*32 iff my slot won
            #pragma unroll
            for (int j = 0; j < 16; j++)
                if (r == (unsigned)(j * 32)) kv[j] = 0u;
            if (lane == 0) { cand_v[warp * PK + it] = mx; cand_i[warp * PK + it] = widx; }
        }
    }
    __pipeline_wait_prior(0);                      // own W copies landed
    __syncthreads();                               // cand + sW visible to all

    // ---- 2. Merge: ALL warps redundantly reduce 128 candidates -> top16 ----
    int t[16];                                     // uniform within each warp
    unsigned myTop = 0;                            // lane it holds top[it]
    {
        unsigned vv[4], vi[4];
        #pragma unroll
        for (int j = 0; j < 4; j++) {
            vv[j] = cand_v[j * 32 + lane];
            vi[j] = cand_i[j * 32 + lane];
        }
        #pragma unroll
        for (int it = 0; it < PK; it++) {
            unsigned bv = vv[0], bi = vi[0];
            #pragma unroll
            for (int j = 1; j < 4; j++) {
                bool better = (vv[j] > bv) || (vv[j] == bv && vi[j] < bi);
                if (better) { bv = vv[j]; bi = vi[j]; }
            }
            unsigned mx = __reduce_max_sync(FULL, bv);
            unsigned myidx = (bv == mx) ? bi : BIGI;
            unsigned widx  = __reduce_min_sync(FULL, myidx);
            #pragma unroll
            for (int j = 0; j < 4; j++)
                if (vv[j] == mx && vi[j] == widx) { vv[j] = 0u; vi[j] = BIGI; }
            t[it] = (int)widx;
            if (lane == it) myTop = widx;
        }
    }

    // ---- 3. Scatter attention mask A (warp 0; indices in registers) ----
    if (warp == 0 && lane < PK) A_out[b * PN + (int)myTop] = 1.0f / (float)PK;

    // ---- 4. Gather + mean: all 8 warps, 24 lanes x float4 each ----
    const float4* __restrict__ H4 = (const float4*)H;
    float4 m = make_float4(0.f, 0.f, 0.f, 0.f);
    const int d4 = warp * 24 + ((lane < 24) ? lane : 23);   // clamped, in-bounds
    if (lane < 24) {
        #pragma unroll
        for (int j = 0; j < PK; j++) {
            float4 h = __ldcs(&H4[((size_t)b * PN + t[j]) * (PD / 4) + d4]);
            m.x += h.x; m.y += h.y; m.z += h.z; m.w += h.w;
        }
        const float inv = 1.0f / (float)PK;
        m.x *= inv; m.y *= inv; m.z *= inv; m.w *= inv;
    }
    // per-lane partial logits over this lane's 4 columns (m==0 for lane>=24)
    float p[PC];
    #pragma unroll
    for (int c = 0; c < PC; c++) {
        const float* w0 = sW + (d4 * 4) * PC + c;
        p[c] = m.x * w0[0] + m.y * w0[PC] + m.z * w0[2 * PC] + m.w * w0[3 * PC];
    }
    // warp-reduce each class partial
    #pragma unroll
    for (int c = 0; c < PC; c++) {
        #pragma unroll
        for (int o = 16; o > 0; o >>= 1)
            p[c] += __shfl_xor_sync(FULL, p[c], o);
    }
    if (lane == 0) {
        #pragma unroll
        for (int c = 0; c < PC; c++) partial[warp][c] = p[c];
    }
    __syncthreads();

    // ---- 5. Final logits ----
    if (tid < PC) {
        float acc = b_cls[tid];
        #pragma unroll
        for (int w = 0; w < 8; w++) acc += partial[w][tid];
        logits_out[b * PC + tid] = acc;
    }
}

// ---------------------------------------------------------------------------
// Launch
// Inputs (metadata order): H [B,N,D] f32, w_score [D] f32, b_score [] f32,
//                          W_cls [D,C] f32, b_cls [C] f32.
// Output: logits [B,C] (320 floats) followed by A [B,N,1] (131072 floats).
// ---------------------------------------------------------------------------
extern "C" void kernel_launch(void* const* d_in, const int* in_sizes, int n_in,
                              void* d_out, int out_size)
{
    const float* H       = (const float*)d_in[0];
    const float* w_score = (const float*)d_in[1];
    const float* b_score = (const float*)d_in[2];
    const float* W_cls   = (const float*)d_in[3];
    const float* b_cls   = (const float*)d_in[4];

    float* logits_out = (float*)d_out;
    float* A_out      = (float*)d_out + PB * PC;

    const int rows = PB * PN;                 // 131072 rows, 1 warp each
    const int blocks1 = (rows + 7) / 8;       // 16384 blocks of 256
    score_kernel<<<blocks1, 256>>>(H, w_score, b_score, A_out);

    topk_epilogue_kernel<<<PB, 256>>>(H, W_cls, b_cls, logits_out, A_out);
}

// round 10
// speedup vs baseline: 1.5488x; 1.0081x over previous
#include <cuda_runtime.h>
#include <cuda_bf16.h>
#include <cuda_pipeline.h>
#include <math.h>

// Problem constants
#define PB 32
#define PN 4096
#define PD 768
#define PC 10
#define PK 16
#define NBIN 2048          // 11-bit key-prefix histogram
#define CAP 512            // candidate buffer capacity

// Scratch: per-(b,n) pre-flipped scores (monotone u32). 512 KB.
__device__ unsigned g_scores_u[PB * PN];

// Monotone 32-bit mapping: flip(a) > flip(b)  <=>  a > b (as floats)
__device__ __forceinline__ unsigned flip_f32(float s) {
    unsigned u = __float_as_uint(s);
    return (u & 0x80000000u) ? ~u : (u | 0x80000000u);
}

// ---------------------------------------------------------------------------
// Kernel 1: scores s[b,n] = dot(H[b,n,:], w) + b_score. One warp per row.
// H streamed with __ldcs so it does not evict g_scores/A from L2.
// Measured 7.0 TB/s — at HBM roofline, untouched.
// ---------------------------------------------------------------------------
__global__ void __launch_bounds__(256) score_kernel(
    const float* __restrict__ H,
    const float* __restrict__ w_score,
    const float* __restrict__ b_score,
    float* __restrict__ A_out)
{
    const int tid_global = blockIdx.x * blockDim.x + threadIdx.x;
    const int warp = tid_global >> 5;
    const int lane = threadIdx.x & 31;

    if (tid_global < PB * PN) A_out[tid_global] = 0.0f;
    if (warp >= PB * PN) return;

    const float4* __restrict__ h4 = (const float4*)(H + (size_t)warp * PD);
    const float4* __restrict__ w4 = (const float4*)w_score;

    float sum = 0.0f;
    #pragma unroll
    for (int k = 0; k < PD / 128; k++) {
        float4 a = __ldcs(&h4[lane + k * 32]);
        float4 b = __ldg(&w4[lane + k * 32]);
        sum += a.x * b.x + a.y * b.y + a.z * b.z + a.w * b.w;
    }
    #pragma unroll
    for (int o = 16; o > 0; o >>= 1)
        sum += __shfl_down_sync(0xFFFFFFFFu, sum, o);

    if (lane == 0) g_scores_u[warp] = flip_f32(sum + b_score[0]);
}

// ---------------------------------------------------------------------------
// Kernel 2: histogram-threshold top-16 + A scatter + gather/mean + classifier.
// 1 CTA per batch, 256 threads.
// ---------------------------------------------------------------------------
__global__ void __launch_bounds__(256) topk_epilogue_kernel(
    const float* __restrict__ H,
    const float* __restrict__ W_cls,   // [D, C] row-major
    const float* __restrict__ b_cls,   // [C]
    float* __restrict__ logits_out,    // d_out, size PB*PC
    float* __restrict__ A_out)         // d_out + PB*PC, size PB*PN
{
    const int b    = blockIdx.x;
    const int tid  = threadIdx.x;
    const int warp = tid >> 5;
    const int lane = tid & 31;
    const unsigned FULL = 0xFFFFFFFFu;

    __shared__ __align__(16) float sW[PD * PC];       // 30720 B
    __shared__ unsigned hist[NBIN];                   // 8192 B
    __shared__ unsigned part[256];                    // 1024 B
    __shared__ unsigned long long candbuf[CAP];       // 4096 B
    __shared__ unsigned sT, ccnt;
    __shared__ int topS[PK];
    __shared__ float partial[8][PC];

    // ---- 0. W_cls -> smem prefetch; zero hist/ccnt ----
    {
        const float4* __restrict__ Wg = (const float4*)W_cls;
        float4* Ws = (float4*)sW;
        #pragma unroll
        for (int i = 0; i < 8; i++) {
            int idx = tid + i * 256;
            if (idx < (PD * PC) / 4)
                __pipeline_memcpy_async(&Ws[idx], &Wg[idx], 16);
        }
        __pipeline_commit();
    }
    #pragma unroll
    for (int i = 0; i < NBIN / 256; i++) hist[tid + i * 256] = 0u;
    if (tid == 0) ccnt = 0u;
    __syncthreads();

    // ---- 1. Load 16 keys/thread + conflict-aggregated histogram ----
    unsigned kv[16];
    const unsigned* __restrict__ sb = g_scores_u + b * PN;
    #pragma unroll
    for (int j = 0; j < 16; j++) kv[j] = sb[j * 256 + tid];   // coalesced
    #pragma unroll
    for (int j = 0; j < 16; j++) {
        unsigned bin = kv[j] >> 21;
        unsigned mk  = __match_any_sync(FULL, bin);
        if (lane == __ffs(mk) - 1) atomicAdd(&hist[bin], (unsigned)__popc(mk));
    }
    __syncthreads();

    // ---- 2. Per-thread partial bin sums ----
    {
        unsigned s = 0;
        #pragma unroll
        for (int i = 0; i < NBIN / 256; i++) s += hist[tid * (NBIN / 256) + i];
        part[tid] = s;
    }
    __syncthreads();

    // ---- 3. Warp 0: find threshold bin T (largest bin with suffix >= 16) ----
    if (warp == 0) {
        unsigned pa = 0;                                // lane covers bins [lane*64,(lane+1)*64)
        #pragma unroll
        for (int i = 0; i < 8; i++) pa += part[lane * 8 + i];
        unsigned sfx = pa;
        #pragma unroll
        for (int o = 1; o < 32; o <<= 1) {
            unsigned u = __shfl_down_sync(FULL, sfx, o);
            if (lane + o < 32) sfx += u;
        }
        unsigned ball = __ballot_sync(FULL, sfx >= PK);
        int l1 = 31 - __clz(ball);                      // window lane
        unsigned sfx_next = __shfl_down_sync(FULL, sfx, 1);
        if (lane == 31) sfx_next = 0u;
        unsigned C_above = __shfl_sync(FULL, sfx_next, l1);  // keys in bins >= (l1+1)*64

        int base = l1 * 64;
        unsigned h0 = hist[base + 2 * lane];
        unsigned h1 = hist[base + 2 * lane + 1];
        unsigned tb = h0 + h1;
        unsigned sfx2 = tb;
        #pragma unroll
        for (int o = 1; o < 32; o <<= 1) {
            unsigned u = __shfl_down_sync(FULL, sfx2, o);
            if (lane + o < 32) sfx2 += u;
        }
        unsigned nxt = __shfl_down_sync(FULL, sfx2, 1);
        if (lane == 31) nxt = 0u;
        unsigned s1 = C_above + nxt + h1;               // suffix at bin base+2l+1
        unsigned s0 = s1 + h0;                          // suffix at bin base+2l
        int p = (s1 >= PK) ? (2 * lane + 1) : ((s0 >= PK) ? (2 * lane) : -1);
        int Toff = __reduce_max_sync(FULL, p);
        if (lane == 0) sT = (unsigned)(base + Toff);
    }
    __syncthreads();

    // ---- 4. Collect candidates with bin >= T ----
    {
        unsigned T = sT;
        #pragma unroll
        for (int j = 0; j < 16; j++) {
            if ((kv[j] >> 21) >= T) {
                unsigned pos = atomicAdd(&ccnt, 1u);
                if (pos < CAP) {
                    unsigned gidx = (unsigned)(j * 256 + tid);
                    candbuf[pos] = ((unsigned long long)kv[j] << 32) | (0xFFFFFFFFu - gidx);
                }
            }
        }
    }
    __pipeline_wait_prior(0);
    __syncthreads();

    // ---- 5. Exact top-16 of candidates ----
    int cc = (int)ccnt; if (cc > CAP) cc = CAP;
    int t[PK]; unsigned myTop = 0;
    if (cc <= 64) {
        // Bitonic sort 64 (ascending of ~packed == descending of packed),
        // run redundantly by all warps. pos p0 = lane, p1 = lane + 32.
        unsigned long long w0 = (lane      < cc) ? ~candbuf[lane]      : ~0ull;
        unsigned long long w1 = (lane + 32 < cc) ? ~candbuf[lane + 32] : ~0ull;
        #pragma unroll
        for (int k = 2; k <= 64; k <<= 1) {
            #pragma unroll
            for (int j = k >> 1; j > 0; j >>= 1) {
                if (j == 32) {                          // only at k==64; ascending
                    unsigned long long mn = (w0 < w1) ? w0 : w1;
                    unsigned long long mx = (w0 < w1) ? w1 : w0;
                    w0 = mn; w1 = mx;
                } else {
                    {
                        unsigned long long y = __shfl_xor_sync(FULL, w0, j);
                        int p = lane;
                        bool keepmin = (((p & k) == 0) == ((p & j) == 0));
                        unsigned long long mn = (w0 < y) ? w0 : y;
                        unsigned long long mx = (w0 < y) ? y : w0;
                        w0 = keepmin ? mn : mx;
                    }
                    {
                        unsigned long long y = __shfl_xor_sync(FULL, w1, j);
                        int p = lane + 32;
                        bool keepmin = (((p & k) == 0) == ((p & j) == 0));
                        unsigned long long mn = (w1 < y) ? w1 : y;
                        unsigned long long mx = (w1 < y) ? y : w1;
                        w1 = keepmin ? mn : mx;
                    }
                }
            }
        }
        // low 32 bits of w0 == gidx (since ~(0xFFFFFFFF - gidx) == gidx)
        myTop = (unsigned)w0;                           // valid for lanes 0..15
        #pragma unroll
        for (int j = 0; j < PK; j++) t[j] = (int)__shfl_sync(FULL, myTop, j);
    } else {
        // Rare fallback: iterative selection over <=CAP candidates (warp 0)
        if (warp == 0) {
            unsigned long long v[16];
            #pragma unroll
            for (int j = 0; j < 16; j++) {
                int i = lane + j * 32;
                v[j] = (i < cc) ? candbuf[i] : 0ull;
            }
            #pragma unroll
            for (int it = 0; it < PK; it++) {
                unsigned long long bk = v[0];
                #pragma unroll
                for (int j = 1; j < 16; j++) bk = (v[j] > bk) ? v[j] : bk;
                unsigned long long mx = bk;
                #pragma unroll
                for (int o = 16; o > 0; o >>= 1) {
                    unsigned long long q = __shfl_xor_sync(FULL, mx, o);
                    mx = (q > mx) ? q : mx;
                }
                #pragma unroll
                for (int j = 0; j < 16; j++) if (v[j] == mx) v[j] = 0ull;
                if (lane == 0) topS[it] = (int)(0xFFFFFFFFu - (unsigned)mx);
            }
        }
        __syncthreads();
        #pragma unroll
        for (int j = 0; j < PK; j++) t[j] = topS[j];
        myTop = (lane < PK) ? (unsigned)topS[lane] : 0u;
    }

    // ---- 6. Scatter attention mask A ----
    if (warp == 0 && lane < PK) A_out[b * PN + (int)myTop] = 1.0f / (float)PK;

    // ---- 7. Gather + mean (all warps, 24 lanes x float4) + partial GEMV ----
    const float4* __restrict__ H4 = (const float4*)H;
    float4 m = make_float4(0.f, 0.f, 0.f, 0.f);
    const int d4 = warp * 24 + ((lane < 24) ? lane : 23);
    if (lane < 24) {
        #pragma unroll
        for (int j = 0; j < PK; j++) {
            float4 h = __ldcs(&H4[((size_t)b * PN + t[j]) * (PD / 4) + d4]);
            m.x += h.x; m.y += h.y; m.z += h.z; m.w += h.w;
        }
        const float inv = 1.0f / (float)PK;
        m.x *= inv; m.y *= inv; m.z *= inv; m.w *= inv;
    }
    float p[PC];
    #pragma unroll
    for (int c = 0; c < PC; c++) {
        const float* w0 = sW + (d4 * 4) * PC + c;
        p[c] = m.x * w0[0] + m.y * w0[PC] + m.z * w0[2 * PC] + m.w * w0[3 * PC];
    }
    #pragma unroll
    for (int c = 0; c < PC; c++) {
        #pragma unroll
        for (int o = 16; o > 0; o >>= 1)
            p[c] += __shfl_xor_sync(FULL, p[c], o);
    }
    if (lane == 0) {
        #pragma unroll
        for (int c = 0; c < PC; c++) partial[warp][c] = p[c];
    }
    __syncthreads();

    // ---- 8. Final logits ----
    if (tid < PC) {
        float acc = b_cls[tid];
        #pragma unroll
        for (int w = 0; w < 8; w++) acc += partial[w][tid];
        logits_out[b * PC + tid] = acc;
    }
}

// ---------------------------------------------------------------------------
// Launch
// Inputs (metadata order): H [B,N,D] f32, w_score [D] f32, b_score [] f32,
//                          W_cls [D,C] f32, b_cls [C] f32.
// Output: logits [B,C] (320 floats) followed by A [B,N,1] (131072 floats).
// ---------------------------------------------------------------------------
extern "C" void kernel_launch(void* const* d_in, const int* in_sizes, int n_in,
                              void* d_out, int out_size)
{
    const float* H       = (const float*)d_in[0];
    const float* w_score = (const float*)d_in[1];
    const float* b_score = (const float*)d_in[2];
    const float* W_cls   = (const float*)d_in[3];
    const float* b_cls   = (const float*)d_in[4];

    float* logits_out = (float*)d_out;
    float* A_out      = (float*)d_out + PB * PC;

    const int rows = PB * PN;
    const int blocks1 = (rows + 7) / 8;
    score_kernel<<<blocks1, 256>>>(H, w_score, b_score, A_out);

    topk_epilogue_kernel<<<PB, 256>>>(H, W_cls, b_cls, logits_out, A_out);
}